// round 12
// baseline (speedup 1.0000x reference)
#include <cuda_runtime.h>
#include <math.h>
#include <stdint.h>

#define T_LEN 8192
#define HALF  4096
#define CH    128
#define BATCH 16
#define NSIG  (BATCH * CH)

#define KSPLIT 16
#define KC     32                          // fp32 per chunk = 128 B rows
#define NCHUNK ((T_LEN / KSPLIT) / KC)     // 16
#define ROWB   144                         // 128B data + 16B pad (conflict-free)
#define BOFF   (128 * ROWB)                // 18432
#define BUFB   (2 * 128 * ROWB)            // 36864 per buffer

// Scratch (alloc-free rule: __device__ globals)
__device__ __align__(16) float2 g_tw[HALF];                   // twiddle table: 32 KB
__device__ float g_c[(size_t)BATCH * CH * T_LEN];             // cos(phase): 64 MB
__device__ float g_s[(size_t)BATCH * CH * T_LEN];             // sin(phase): 64 MB
__device__ float g_gram[(size_t)KSPLIT * BATCH * 3 * CH * CH];// tiles: 50 MB

// ===========================================================================
// PTX helpers
// ===========================================================================
__device__ __forceinline__ uint32_t smem_u32(const void* p) {
    uint32_t a;
    asm("{ .reg .u64 t; cvta.to.shared.u64 t, %1; cvt.u32.u64 %0, t; }"
        : "=r"(a) : "l"(p));
    return a;
}
__device__ __forceinline__ void mma_tf32(float* d, const uint32_t* a,
                                         const uint32_t* b) {
    asm volatile(
        "mma.sync.aligned.m16n8k8.row.col.f32.tf32.tf32.f32 "
        "{%0,%1,%2,%3}, {%4,%5,%6,%7}, {%8,%9}, {%0,%1,%2,%3};"
        : "+f"(d[0]), "+f"(d[1]), "+f"(d[2]), "+f"(d[3])
        : "r"(a[0]), "r"(a[1]), "r"(a[2]), "r"(a[3]), "r"(b[0]), "r"(b[1]));
}
__device__ __forceinline__ void cp16(uint32_t smem, const void* g) {
    asm volatile("cp.async.cg.shared.global [%0], [%1], 16;"
                 :: "r"(smem), "l"(g) : "memory");
}
#define CP_COMMIT() asm volatile("cp.async.commit_group;" ::: "memory")
#define CP_WAIT1()  asm volatile("cp.async.wait_group 1;" ::: "memory")
#define CP_WAIT0()  asm volatile("cp.async.wait_group 0;" ::: "memory")
__device__ __forceinline__ uint32_t lds32(uint32_t addr) {
    uint32_t v;
    asm volatile("ld.shared.b32 %0, [%1];" : "=r"(v) : "r"(addr));
    return v;
}
__device__ __forceinline__ uint32_t f2tf32(float f) {
    uint32_t u;
    asm("cvt.rna.tf32.f32 %0, %1;" : "=r"(u) : "f"(f));
    return u;
}

// ===========================================================================
// Kernel 0: twiddle table init (once per launch; ~2 us).
// tw[t] = exp(-2*pi*i*t/T_LEN), computed with sincospi for accuracy.
// ===========================================================================
__global__ void twiddle_init() {
    const int t = blockIdx.x * blockDim.x + threadIdx.x;
    if (t < HALF) {
        float s, c;
        sincospif(-2.0f * (float)t / (float)T_LEN, &s, &c);
        g_tw[t] = make_float2(c, s);
    }
}

// ===========================================================================
// Kernel 1: register-resident FFT (R9 body, twiddle hoisting). Twiddles now
// cp.async'd from the precomputed global table (no per-block sincosf).
// Direct tf32 epilogue: cvt.rna once, coalesced STG.32.
// ===========================================================================
__device__ __forceinline__ int swz(int i) { return i ^ ((i >> 5) & 31); }

template<int P, int LB, int FWD>
__device__ __forceinline__ void stage_one(float2 v[16], int base,
                                          const float2* __restrict__ tw) {
    const int s  = P + LB;
    const int bm = base & ((1 << s) - 1);
    float2 wc[(LB < 3) ? (1 << LB) : 1];
    if (LB < 3) {
#pragma unroll
        for (int q = 0; q < (1 << LB); q++)
            wc[q] = tw[(bm + (q << P)) << (12 - s)];
    }
#pragma unroll
    for (int rr = 0; rr < 16; rr++) {
        if ((rr >> LB) & 1) continue;
        const int r1 = rr | (1 << LB);
        float2 w;
        if (LB < 3) w = wc[rr & ((1 << LB) - 1)];
        else        w = tw[(bm + ((rr & 7) << P)) << (12 - s)];
        float2 a = v[rr], b = v[r1];
        if (FWD) {
            v[rr] = make_float2(a.x + b.x, a.y + b.y);
            float2 d = make_float2(a.x - b.x, a.y - b.y);
            v[r1] = make_float2(d.x * w.x - d.y * w.y, d.x * w.y + d.y * w.x);
        } else {
            float2 tt = make_float2(b.x * w.x + b.y * w.y, b.y * w.x - b.x * w.y);
            v[rr] = make_float2(a.x + tt.x, a.y + tt.y);
            v[r1] = make_float2(a.x - tt.x, a.y - tt.y);
        }
    }
}

template<int P, int FWD, int LBLO, int LBHI>
__device__ __forceinline__ void stages(float2 v[16], int base,
                                       const float2* __restrict__ tw) {
    if (FWD) {
        if (LBHI >= 3 && 3 >= LBLO) stage_one<P, 3, 1>(v, base, tw);
        if (LBHI >= 2 && 2 >= LBLO) stage_one<P, 2, 1>(v, base, tw);
        if (LBHI >= 1 && 1 >= LBLO) stage_one<P, 1, 1>(v, base, tw);
        if (LBHI >= 0 && 0 >= LBLO) stage_one<P, 0, 1>(v, base, tw);
    } else {
        if (LBLO <= 0 && 0 <= LBHI) stage_one<P, 0, 0>(v, base, tw);
        if (LBLO <= 1 && 1 <= LBHI) stage_one<P, 1, 0>(v, base, tw);
        if (LBLO <= 2 && 2 <= LBHI) stage_one<P, 2, 0>(v, base, tw);
        if (LBLO <= 3 && 3 <= LBHI) stage_one<P, 3, 0>(v, base, tw);
    }
}

extern __shared__ float2 smm[];   // [0..8191]=exchange, [8192..12287]=twiddles

__global__ void __launch_bounds__(512) fft_kernel(const float* __restrict__ x) {
    float2* sm = smm;
    float2* tw = smm + T_LEN;
    const int tid = threadIdx.x;
    const long long gbase = (long long)blockIdx.x * T_LEN;

    // Pull precomputed twiddle table into smem (32 KB, 4 cp16/thread),
    // overlapped with the input global loads below.
    {
        const uint32_t twa = smem_u32(tw);
#pragma unroll
        for (int i = 0; i < 4; i++) {
            const int qidx = tid + i * 512;              // 16B quad index, 0..2047
            cp16(twa + qidx * 16, (const char*)g_tw + qidx * 16);
        }
        CP_COMMIT();
    }

    const int baseA = tid;                                  // P=9
    const int baseB = ((tid >> 5) << 9) + (tid & 31);       // P=5
    const int baseC = ((tid >> 1) << 5) + (tid & 1);        // P=1
    const int baseD = tid << 4;                             // P=0
    const int baseE = ((tid >> 4) << 8) + (tid & 15);       // P=4
    const int baseF = ((tid >> 8) << 12) + (tid & 255);     // P=8

    float2 v[16];
#pragma unroll
    for (int r = 0; r < 16; r++)
        v[r] = make_float2(x[gbase + tid + r * 512], 0.0f);
    CP_WAIT0();
    __syncthreads();

    stages<9, 1, 0, 3>(v, baseA, tw);
#pragma unroll
    for (int r = 0; r < 16; r++) sm[swz(baseA + (r << 9))] = v[r];
    __syncthreads();
#pragma unroll
    for (int r = 0; r < 16; r++) v[r] = sm[swz(baseB + (r << 5))];
    __syncthreads();

    stages<5, 1, 0, 3>(v, baseB, tw);
#pragma unroll
    for (int r = 0; r < 16; r++) sm[swz(baseB + (r << 5))] = v[r];
    __syncthreads();
#pragma unroll
    for (int r = 0; r < 16; r++) v[r] = sm[swz(baseC + (r << 1))];
    __syncthreads();

    stages<1, 1, 0, 3>(v, baseC, tw);
#pragma unroll
    for (int r = 0; r < 16; r++) sm[swz(baseC + (r << 1))] = v[r];
    __syncthreads();
#pragma unroll
    for (int r = 0; r < 16; r++) v[r] = sm[swz(baseD + r)];
    __syncthreads();

#pragma unroll
    for (int r = 0; r < 16; r += 2) {
        float2 s0 = make_float2(v[r].x + v[r + 1].x, v[r].y + v[r + 1].y);
        v[r] = s0; v[r + 1] = s0;
    }

    stages<0, 0, 1, 3>(v, baseD, tw);
#pragma unroll
    for (int r = 0; r < 16; r++) sm[swz(baseD + r)] = v[r];
    __syncthreads();
#pragma unroll
    for (int r = 0; r < 16; r++) v[r] = sm[swz(baseE + (r << 4))];
    __syncthreads();

    stages<4, 0, 0, 3>(v, baseE, tw);
#pragma unroll
    for (int r = 0; r < 16; r++) sm[swz(baseE + (r << 4))] = v[r];
    __syncthreads();
#pragma unroll
    for (int r = 0; r < 16; r++) v[r] = sm[swz(baseF + (r << 8))];
    __syncthreads();

    stages<8, 0, 0, 3>(v, baseF, tw);
#pragma unroll
    for (int r = 0; r < 16; r++) sm[swz(baseF + (r << 8))] = v[r];
    __syncthreads();
#pragma unroll
    for (int r = 0; r < 16; r++) v[r] = sm[swz(baseA + (r << 9))];
    __syncthreads();

    stages<9, 0, 3, 3>(v, baseA, tw);

    // ---- epilogue: normalize, round to tf32, direct coalesced stores ----
    const size_t rowb = (size_t)blockIdx.x * T_LEN;
#pragma unroll
    for (int r = 0; r < 16; r++) {
        const int t = tid + r * 512;
        float2 u = v[r];
        float m2 = u.x * u.x + u.y * u.y;
        float cx, sx;
        if (m2 > 0.0f) {
            float inv = rsqrtf(m2);
            cx = u.x * inv; sx = u.y * inv;
        } else {
            cx = 1.0f; sx = 0.0f;
        }
        g_c[rowb + t] = __uint_as_float(f2tf32(cx));
        g_s[rowb + t] = __uint_as_float(f2tf32(sx));
    }
}

// ===========================================================================
// Kernel 2: tf32 single-chain Gram via mma.sync.m16n8k8 (unchanged from R11).
// CTA = (ks, q, b). q: 0=CC (A=B=cos), 1=SS (A=B=sin), 2=SC (A=sin, B=cos).
// ===========================================================================
extern __shared__ __align__(128) char gsm[];   // 2 * BUFB = 73728 B

__global__ void __launch_bounds__(256, 2) gram_tf32() {
    const int tid  = threadIdx.x;
    const int wid  = tid >> 5;
    const int lane = tid & 31;
    const int ks   = blockIdx.x;
    const int q    = blockIdx.y;
    const int b    = blockIdx.z;
    const bool diag = (q < 2);

    const float* __restrict__ srcA = (q == 0) ? g_c : g_s;
    const float* __restrict__ srcB = (q == 1) ? g_s : g_c;

    const uint32_t sb = smem_u32(gsm);
    const size_t k0 = (size_t)ks * (T_LEN / KSPLIT);

    const int qi  = tid & 7;
    const int r32 = tid >> 3;
    const int npass = diag ? 4 : 8;

    const float* psrc[8]; uint32_t pdst[8];
#pragma unroll
    for (int p = 0; p < 8; p++) {
        const int row = r32 + (p & 3) * 32;
        const float* srcm = (p < 4) ? srcA : srcB;
        psrc[p] = srcm + (size_t)(b * CH + row) * T_LEN + k0 + qi * 4;
        pdst[p] = (uint32_t)((p < 4 ? 0 : BOFF) + row * ROWB + qi * 16);
    }

    auto load_chunk = [&](int c) {
        const uint32_t bufb = sb + (uint32_t)((c & 1) * BUFB);
        const int kofs = c * KC;
#pragma unroll
        for (int p = 0; p < 8; p++) {
            if (p >= npass) break;
            cp16(bufb + pdst[p], psrc[p] + kofs);
        }
        CP_COMMIT();
    };

    const int mrow0 = (wid >> 2) * 64;
    const int ncol0 = (wid & 3) * 32;
    const uint32_t bOfs = diag ? 0u : (uint32_t)BOFF;

    float acc[4][4][4];
#pragma unroll
    for (int mt = 0; mt < 4; mt++)
#pragma unroll
        for (int nt = 0; nt < 4; nt++)
#pragma unroll
            for (int e = 0; e < 4; e++) acc[mt][nt][e] = 0.0f;

    const int lg = lane >> 2;
    const int lk = lane & 3;

    load_chunk(0);
    for (int c = 0; c < NCHUNK; c++) {
        if (c + 1 < NCHUNK) { load_chunk(c + 1); CP_WAIT1(); }
        else                { CP_WAIT0(); }
        __syncthreads();

        const uint32_t bufb = sb + (uint32_t)((c & 1) * BUFB);
#pragma unroll
        for (int kstep = 0; kstep < KC / 8; kstep++) {
            const uint32_t kb = (uint32_t)(kstep * 32 + lk * 4);
            uint32_t bfr[4][2];
#pragma unroll
            for (int nt = 0; nt < 4; nt++) {
                const uint32_t ba =
                    bufb + bOfs + (uint32_t)((ncol0 + nt * 8 + lg) * ROWB) + kb;
                bfr[nt][0] = lds32(ba);
                bfr[nt][1] = lds32(ba + 16);
            }
#pragma unroll
            for (int mt = 0; mt < 4; mt++) {
                const uint32_t aa =
                    bufb + (uint32_t)((mrow0 + mt * 16 + lg) * ROWB) + kb;
                uint32_t af[4];
                af[0] = lds32(aa);
                af[1] = lds32(aa + 8 * ROWB);
                af[2] = lds32(aa + 16);
                af[3] = lds32(aa + 8 * ROWB + 16);
#pragma unroll
                for (int nt = 0; nt < 4; nt++)
                    mma_tf32(acc[mt][nt], af, bfr[nt]);
            }
        }
        __syncthreads();
    }

    float* __restrict__ G =
        g_gram + ((size_t)((ks * BATCH + b) * 3 + q)) * (CH * CH);
    const int r0 = lane >> 2;
    const int c0 = (lane & 3) * 2;
#pragma unroll
    for (int mt = 0; mt < 4; mt++) {
        const int row = mrow0 + mt * 16 + r0;
#pragma unroll
        for (int nt = 0; nt < 4; nt++) {
            const int col = ncol0 + nt * 8 + c0;
            *(float2*)(G + row * CH + col) =
                make_float2(acc[mt][nt][0], acc[mt][nt][1]);
            *(float2*)(G + (row + 8) * CH + col) =
                make_float2(acc[mt][nt][2], acc[mt][nt][3]);
        }
    }
}

// ===========================================================================
// Kernel 3: combine K-splits; Re = CC+SS, Im = SC_ij - SC_ji; PLV = |.|/T.
// ===========================================================================
__global__ void finalize_kernel(float* __restrict__ out) {
    const int idx = blockIdx.x * blockDim.x + threadIdx.x;
    if (idx >= BATCH * CH * CH) return;
    const int b  = idx >> 14;
    const int ij = idx & 16383;
    const int i  = ij >> 7;
    const int j  = ij & 127;
    float re = 0.0f, im = 0.0f;
#pragma unroll
    for (int ks = 0; ks < KSPLIT; ks++) {
        const float* __restrict__ base =
            g_gram + ((size_t)((ks * BATCH + b) * 3)) * (CH * CH);
        re += base[ij] + base[CH * CH + ij];                       // CC + SS
        im += base[2 * CH * CH + i * CH + j]
            - base[2 * CH * CH + j * CH + i];                      // SC - SC^T
    }
    out[idx] = sqrtf(re * re + im * im) * (1.0f / (float)T_LEN);
}

// ===========================================================================
extern "C" void kernel_launch(void* const* d_in, const int* in_sizes, int n_in,
                              void* d_out, int out_size) {
    const float* x = (const float*)d_in[0];
    float* out = (float*)d_out;

    const int fft_smem = (T_LEN + HALF) * (int)sizeof(float2);  // 96 KB
    cudaFuncSetAttribute(fft_kernel, cudaFuncAttributeMaxDynamicSharedMemorySize,
                         fft_smem);
    cudaFuncSetAttribute(gram_tf32, cudaFuncAttributeMaxDynamicSharedMemorySize,
                         2 * BUFB);

    twiddle_init<<<(HALF + 255) / 256, 256>>>();
    fft_kernel<<<NSIG, 512, fft_smem>>>(x);
    gram_tf32<<<dim3(KSPLIT, 3, BATCH), 256, 2 * BUFB>>>();
    finalize_kernel<<<(BATCH * CH * CH + 255) / 256, 256>>>(out);
}

// round 13
// speedup vs baseline: 1.1907x; 1.1907x over previous
#include <cuda_runtime.h>
#include <math.h>
#include <stdint.h>

#define T_LEN 8192
#define HALF  4096
#define CH    128
#define BATCH 16
#define NSIG  (BATCH * CH)

#define KSPLIT 16
#define KC     32                          // fp32 per chunk = 128 B rows
#define NCHUNK ((T_LEN / KSPLIT) / KC)     // 16
#define ROWB   144                         // 128B data + 16B pad (conflict-free)
#define BOFF   (128 * ROWB)                // 18432
#define BUFB   (2 * 128 * ROWB)            // 36864 per buffer

// Scratch (alloc-free rule: __device__ globals)
__device__ float g_c[(size_t)BATCH * CH * T_LEN];             // cos(phase): 64 MB
__device__ float g_s[(size_t)BATCH * CH * T_LEN];             // sin(phase): 64 MB
__device__ float g_gram[(size_t)KSPLIT * BATCH * 3 * CH * CH];// tiles: 50 MB

// ===========================================================================
// PTX helpers
// ===========================================================================
__device__ __forceinline__ uint32_t smem_u32(const void* p) {
    uint32_t a;
    asm("{ .reg .u64 t; cvta.to.shared.u64 t, %1; cvt.u32.u64 %0, t; }"
        : "=r"(a) : "l"(p));
    return a;
}
__device__ __forceinline__ void mma_tf32(float* d, const uint32_t* a,
                                         const uint32_t* b) {
    asm volatile(
        "mma.sync.aligned.m16n8k8.row.col.f32.tf32.tf32.f32 "
        "{%0,%1,%2,%3}, {%4,%5,%6,%7}, {%8,%9}, {%0,%1,%2,%3};"
        : "+f"(d[0]), "+f"(d[1]), "+f"(d[2]), "+f"(d[3])
        : "r"(a[0]), "r"(a[1]), "r"(a[2]), "r"(a[3]), "r"(b[0]), "r"(b[1]));
}
__device__ __forceinline__ void cp16(uint32_t smem, const void* g) {
    asm volatile("cp.async.cg.shared.global [%0], [%1], 16;"
                 :: "r"(smem), "l"(g) : "memory");
}
#define CP_COMMIT() asm volatile("cp.async.commit_group;" ::: "memory")
#define CP_WAIT1()  asm volatile("cp.async.wait_group 1;" ::: "memory")
#define CP_WAIT0()  asm volatile("cp.async.wait_group 0;" ::: "memory")
__device__ __forceinline__ uint32_t lds32(uint32_t addr) {
    uint32_t v;
    asm volatile("ld.shared.b32 %0, [%1];" : "=r"(v) : "r"(addr));
    return v;
}
__device__ __forceinline__ uint32_t f2tf32(float f) {
    uint32_t u;
    asm("cvt.rna.tf32.f32 %0, %1;" : "=r"(u) : "f"(f));
    return u;
}

// ===========================================================================
// Kernel 1: two-channel real-packed FFT.
// z = x_c0 + i*x_c1 -> Z (13 fwd stages). Then:
//   u = ifft(M  * Z), M  keeps k <  N/2  <=> bit-rev position p even
//   w = ifft(M~ * Z), M~ keeps k=0,k>N/2 <=> p odd except p=1, plus p=0
//   xa_c0 = (u + conj(w))/2 ;  xa_c1 = ((ui+wi) - i(ur-wr))/2
// 39 stages per 2 channels instead of 52. Normalize -> tf32 -> store.
// ===========================================================================
__device__ __forceinline__ int swz(int i) { return i ^ ((i >> 5) & 31); }

template<int P, int LB, int FWD>
__device__ __forceinline__ void stage_one(float2 v[16], int base,
                                          const float2* __restrict__ tw) {
    const int s  = P + LB;
    const int bm = base & ((1 << s) - 1);
    float2 wc[(LB < 3) ? (1 << LB) : 1];
    if (LB < 3) {
#pragma unroll
        for (int q = 0; q < (1 << LB); q++)
            wc[q] = tw[(bm + (q << P)) << (12 - s)];
    }
#pragma unroll
    for (int rr = 0; rr < 16; rr++) {
        if ((rr >> LB) & 1) continue;
        const int r1 = rr | (1 << LB);
        float2 w;
        if (LB < 3) w = wc[rr & ((1 << LB) - 1)];
        else        w = tw[(bm + ((rr & 7) << P)) << (12 - s)];
        float2 a = v[rr], b = v[r1];
        if (FWD) {
            v[rr] = make_float2(a.x + b.x, a.y + b.y);
            float2 d = make_float2(a.x - b.x, a.y - b.y);
            v[r1] = make_float2(d.x * w.x - d.y * w.y, d.x * w.y + d.y * w.x);
        } else {
            float2 tt = make_float2(b.x * w.x + b.y * w.y, b.y * w.x - b.x * w.y);
            v[rr] = make_float2(a.x + tt.x, a.y + tt.y);
            v[r1] = make_float2(a.x - tt.x, a.y - tt.y);
        }
    }
}

template<int P, int FWD, int LBLO, int LBHI>
__device__ __forceinline__ void stages(float2 v[16], int base,
                                       const float2* __restrict__ tw) {
    if (FWD) {
        if (LBHI >= 3 && 3 >= LBLO) stage_one<P, 3, 1>(v, base, tw);
        if (LBHI >= 2 && 2 >= LBLO) stage_one<P, 2, 1>(v, base, tw);
        if (LBHI >= 1 && 1 >= LBLO) stage_one<P, 1, 1>(v, base, tw);
        if (LBHI >= 0 && 0 >= LBLO) stage_one<P, 0, 1>(v, base, tw);
    } else {
        if (LBLO <= 0 && 0 <= LBHI) stage_one<P, 0, 0>(v, base, tw);
        if (LBLO <= 1 && 1 <= LBHI) stage_one<P, 1, 0>(v, base, tw);
        if (LBLO <= 2 && 2 <= LBHI) stage_one<P, 2, 0>(v, base, tw);
        if (LBLO <= 3 && 3 <= LBHI) stage_one<P, 3, 0>(v, base, tw);
    }
}

extern __shared__ float2 smm[];
// layout (float2 units): [0..8191] exchange, [8192..12287] twiddles,
// [12288..20479] Zsave, [20480..28671] Usave  -> 229376 bytes total

__device__ __forceinline__ void inv_chain(float2 v[16], const float2* tw,
                                          float2* sm, int baseD, int baseE,
                                          int baseF, int baseA) {
    stages<0, 0, 0, 3>(v, baseD, tw);       // s = 0..3
#pragma unroll
    for (int r = 0; r < 16; r++) sm[swz(baseD + r)] = v[r];
    __syncthreads();
#pragma unroll
    for (int r = 0; r < 16; r++) v[r] = sm[swz(baseE + (r << 4))];
    __syncthreads();
    stages<4, 0, 0, 3>(v, baseE, tw);       // s = 4..7
#pragma unroll
    for (int r = 0; r < 16; r++) sm[swz(baseE + (r << 4))] = v[r];
    __syncthreads();
#pragma unroll
    for (int r = 0; r < 16; r++) v[r] = sm[swz(baseF + (r << 8))];
    __syncthreads();
    stages<8, 0, 0, 3>(v, baseF, tw);       // s = 8..11
#pragma unroll
    for (int r = 0; r < 16; r++) sm[swz(baseF + (r << 8))] = v[r];
    __syncthreads();
#pragma unroll
    for (int r = 0; r < 16; r++) v[r] = sm[swz(baseA + (r << 9))];
    __syncthreads();
    stages<9, 0, 3, 3>(v, baseA, tw);       // s = 12  -> natural order
}

__global__ void __launch_bounds__(512) fft_kernel(const float* __restrict__ x) {
    float2* sm  = smm;
    float2* tw  = smm + T_LEN;
    float2* Zsv = smm + T_LEN + HALF;
    float2* Usv = Zsv + T_LEN;
    const int tid = threadIdx.x;

    for (int t = tid; t < HALF; t += 512) {
        float s, c;
        sincosf(-6.283185307179586e0f * (float)t / (float)T_LEN, &s, &c);
        tw[t] = make_float2(c, s);
    }

    const int baseA = tid;                                  // P=9
    const int baseB = ((tid >> 5) << 9) + (tid & 31);       // P=5
    const int baseC = ((tid >> 1) << 5) + (tid & 1);        // P=1
    const int baseD = tid << 4;                             // P=0
    const int baseE = ((tid >> 4) << 8) + (tid & 15);       // P=4
    const int baseF = ((tid >> 8) << 12) + (tid & 255);     // P=8

    // Load z = x_c0 + i*x_c1 (two consecutive channel rows per block)
    const float* __restrict__ xr = x + (size_t)blockIdx.x * 2 * T_LEN;
    float2 v[16];
#pragma unroll
    for (int r = 0; r < 16; r++) {
        const int t = tid + r * 512;
        v[r] = make_float2(xr[t], xr[T_LEN + t]);
    }
    __syncthreads();   // tw ready

    // ---- forward DIF: s = 12..0 (13 stages) ----
    stages<9, 1, 0, 3>(v, baseA, tw);
#pragma unroll
    for (int r = 0; r < 16; r++) sm[swz(baseA + (r << 9))] = v[r];
    __syncthreads();
#pragma unroll
    for (int r = 0; r < 16; r++) v[r] = sm[swz(baseB + (r << 5))];
    __syncthreads();
    stages<5, 1, 0, 3>(v, baseB, tw);
#pragma unroll
    for (int r = 0; r < 16; r++) sm[swz(baseB + (r << 5))] = v[r];
    __syncthreads();
#pragma unroll
    for (int r = 0; r < 16; r++) v[r] = sm[swz(baseC + (r << 1))];
    __syncthreads();
    stages<1, 1, 0, 3>(v, baseC, tw);
#pragma unroll
    for (int r = 0; r < 16; r++) sm[swz(baseC + (r << 1))] = v[r];
    __syncthreads();
#pragma unroll
    for (int r = 0; r < 16; r++) v[r] = sm[swz(baseD + r)];
    __syncthreads();
    stages<0, 1, 0, 0>(v, baseD, tw);       // fwd s=0 -> Z bit-reversed

    // Save Z (thread-private round trip; no syncs needed around it)
#pragma unroll
    for (int r = 0; r < 16; r++) Zsv[swz(baseD + r)] = v[r];

    // ---- u = ifft(M * Z): keep even bit-reversed positions ----
#pragma unroll
    for (int r = 1; r < 16; r += 2) v[r] = make_float2(0.0f, 0.0f);
    inv_chain(v, tw, sm, baseD, baseE, baseF, baseA);
#pragma unroll
    for (int r = 0; r < 16; r++) Usv[swz(baseA + (r << 9))] = v[r];

    // ---- w = ifft(M~ * Z): keep p odd except p=1, plus p=0 ----
#pragma unroll
    for (int r = 0; r < 16; r++) {
        float2 z = Zsv[swz(baseD + r)];
        const int p = baseD + r;
        bool keep = (r & 1) ? (p != 1) : (p == 0);
        v[r] = keep ? z : make_float2(0.0f, 0.0f);
    }
    inv_chain(v, tw, sm, baseD, baseE, baseF, baseA);

    // ---- combine, normalize, store both channels (tf32) ----
    const size_t row0 = (size_t)blockIdx.x * 2 * T_LEN;
#pragma unroll
    for (int r = 0; r < 16; r++) {
        const int t = tid + (r << 9);
        float2 w2 = v[r];
        float2 u2 = Usv[swz(baseA + (r << 9))];
        // xa_c0 = (ur+wr, ui-wi) ; xa_c1 = (ui+wi, wr-ur)   (x0.5 dropped)
        float x1r = u2.x + w2.x, x1i = u2.y - w2.y;
        float x2r = u2.y + w2.y, x2i = w2.x - u2.x;

        float m1 = x1r * x1r + x1i * x1i;
        float c1, s1;
        if (m1 > 0.0f) { float iv = rsqrtf(m1); c1 = x1r * iv; s1 = x1i * iv; }
        else           { c1 = 1.0f; s1 = 0.0f; }
        float m2 = x2r * x2r + x2i * x2i;
        float c2, s2;
        if (m2 > 0.0f) { float iv = rsqrtf(m2); c2 = x2r * iv; s2 = x2i * iv; }
        else           { c2 = 1.0f; s2 = 0.0f; }

        g_c[row0 + t]         = __uint_as_float(f2tf32(c1));
        g_s[row0 + t]         = __uint_as_float(f2tf32(s1));
        g_c[row0 + T_LEN + t] = __uint_as_float(f2tf32(c2));
        g_s[row0 + T_LEN + t] = __uint_as_float(f2tf32(s2));
    }
}

// ===========================================================================
// Kernel 2: tf32 single-chain Gram via mma.sync.m16n8k8 (unchanged from R11).
// CTA = (ks, q, b). q: 0=CC (A=B=cos), 1=SS (A=B=sin), 2=SC (A=sin, B=cos).
// ===========================================================================
extern __shared__ __align__(128) char gsm[];   // 2 * BUFB = 73728 B

__global__ void __launch_bounds__(256, 2) gram_tf32() {
    const int tid  = threadIdx.x;
    const int wid  = tid >> 5;
    const int lane = tid & 31;
    const int ks   = blockIdx.x;
    const int q    = blockIdx.y;
    const int b    = blockIdx.z;
    const bool diag = (q < 2);

    const float* __restrict__ srcA = (q == 0) ? g_c : g_s;
    const float* __restrict__ srcB = (q == 1) ? g_s : g_c;

    const uint32_t sb = smem_u32(gsm);
    const size_t k0 = (size_t)ks * (T_LEN / KSPLIT);

    const int qi  = tid & 7;
    const int r32 = tid >> 3;
    const int npass = diag ? 4 : 8;

    const float* psrc[8]; uint32_t pdst[8];
#pragma unroll
    for (int p = 0; p < 8; p++) {
        const int row = r32 + (p & 3) * 32;
        const float* srcm = (p < 4) ? srcA : srcB;
        psrc[p] = srcm + (size_t)(b * CH + row) * T_LEN + k0 + qi * 4;
        pdst[p] = (uint32_t)((p < 4 ? 0 : BOFF) + row * ROWB + qi * 16);
    }

    auto load_chunk = [&](int c) {
        const uint32_t bufb = sb + (uint32_t)((c & 1) * BUFB);
        const int kofs = c * KC;
#pragma unroll
        for (int p = 0; p < 8; p++) {
            if (p >= npass) break;
            cp16(bufb + pdst[p], psrc[p] + kofs);
        }
        CP_COMMIT();
    };

    const int mrow0 = (wid >> 2) * 64;
    const int ncol0 = (wid & 3) * 32;
    const uint32_t bOfs = diag ? 0u : (uint32_t)BOFF;

    float acc[4][4][4];
#pragma unroll
    for (int mt = 0; mt < 4; mt++)
#pragma unroll
        for (int nt = 0; nt < 4; nt++)
#pragma unroll
            for (int e = 0; e < 4; e++) acc[mt][nt][e] = 0.0f;

    const int lg = lane >> 2;
    const int lk = lane & 3;

    load_chunk(0);
    for (int c = 0; c < NCHUNK; c++) {
        if (c + 1 < NCHUNK) { load_chunk(c + 1); CP_WAIT1(); }
        else                { CP_WAIT0(); }
        __syncthreads();

        const uint32_t bufb = sb + (uint32_t)((c & 1) * BUFB);
#pragma unroll
        for (int kstep = 0; kstep < KC / 8; kstep++) {
            const uint32_t kb = (uint32_t)(kstep * 32 + lk * 4);
            uint32_t bfr[4][2];
#pragma unroll
            for (int nt = 0; nt < 4; nt++) {
                const uint32_t ba =
                    bufb + bOfs + (uint32_t)((ncol0 + nt * 8 + lg) * ROWB) + kb;
                bfr[nt][0] = lds32(ba);
                bfr[nt][1] = lds32(ba + 16);
            }
#pragma unroll
            for (int mt = 0; mt < 4; mt++) {
                const uint32_t aa =
                    bufb + (uint32_t)((mrow0 + mt * 16 + lg) * ROWB) + kb;
                uint32_t af[4];
                af[0] = lds32(aa);
                af[1] = lds32(aa + 8 * ROWB);
                af[2] = lds32(aa + 16);
                af[3] = lds32(aa + 8 * ROWB + 16);
#pragma unroll
                for (int nt = 0; nt < 4; nt++)
                    mma_tf32(acc[mt][nt], af, bfr[nt]);
            }
        }
        __syncthreads();
    }

    float* __restrict__ G =
        g_gram + ((size_t)((ks * BATCH + b) * 3 + q)) * (CH * CH);
    const int r0 = lane >> 2;
    const int c0 = (lane & 3) * 2;
#pragma unroll
    for (int mt = 0; mt < 4; mt++) {
        const int row = mrow0 + mt * 16 + r0;
#pragma unroll
        for (int nt = 0; nt < 4; nt++) {
            const int col = ncol0 + nt * 8 + c0;
            *(float2*)(G + row * CH + col) =
                make_float2(acc[mt][nt][0], acc[mt][nt][1]);
            *(float2*)(G + (row + 8) * CH + col) =
                make_float2(acc[mt][nt][2], acc[mt][nt][3]);
        }
    }
}

// ===========================================================================
// Kernel 3: combine K-splits; Re = CC+SS, Im = SC_ij - SC_ji; PLV = |.|/T.
// ===========================================================================
__global__ void finalize_kernel(float* __restrict__ out) {
    const int idx = blockIdx.x * blockDim.x + threadIdx.x;
    if (idx >= BATCH * CH * CH) return;
    const int b  = idx >> 14;
    const int ij = idx & 16383;
    const int i  = ij >> 7;
    const int j  = ij & 127;
    float re = 0.0f, im = 0.0f;
#pragma unroll
    for (int ks = 0; ks < KSPLIT; ks++) {
        const float* __restrict__ base =
            g_gram + ((size_t)((ks * BATCH + b) * 3)) * (CH * CH);
        re += base[ij] + base[CH * CH + ij];                       // CC + SS
        im += base[2 * CH * CH + i * CH + j]
            - base[2 * CH * CH + j * CH + i];                      // SC - SC^T
    }
    out[idx] = sqrtf(re * re + im * im) * (1.0f / (float)T_LEN);
}

// ===========================================================================
extern "C" void kernel_launch(void* const* d_in, const int* in_sizes, int n_in,
                              void* d_out, int out_size) {
    const float* x = (const float*)d_in[0];
    float* out = (float*)d_out;

    const int fft_smem = (T_LEN + HALF + 2 * T_LEN) * (int)sizeof(float2); // 229376
    cudaFuncSetAttribute(fft_kernel, cudaFuncAttributeMaxDynamicSharedMemorySize,
                         fft_smem);
    cudaFuncSetAttribute(gram_tf32, cudaFuncAttributeMaxDynamicSharedMemorySize,
                         2 * BUFB);

    fft_kernel<<<NSIG / 2, 512, fft_smem>>>(x);
    gram_tf32<<<dim3(KSPLIT, 3, BATCH), 256, 2 * BUFB>>>();
    finalize_kernel<<<(BATCH * CH * CH + 255) / 256, 256>>>(out);
}

// round 14
// speedup vs baseline: 1.4383x; 1.2079x over previous
#include <cuda_runtime.h>
#include <math.h>
#include <stdint.h>

#define T_LEN 8192
#define HALF  4096
#define CH    128
#define BATCH 16
#define NSIG  (BATCH * CH)

#define KSPLIT 16
#define KC     32                          // fp32 per chunk = 128 B rows
#define NCHUNK ((T_LEN / KSPLIT) / KC)     // 16
#define ROWB   144                         // 128B data + 16B pad (conflict-free)
#define BOFF   (128 * ROWB)                // 18432
#define BUFB   (2 * 128 * ROWB)            // 36864 per buffer

// Scratch (alloc-free rule: __device__ globals)
__device__ float g_c[(size_t)BATCH * CH * T_LEN];             // cos(phase): 64 MB
__device__ float g_s[(size_t)BATCH * CH * T_LEN];             // sin(phase): 64 MB
__device__ float g_gram[(size_t)KSPLIT * BATCH * 3 * CH * CH];// tiles: 50 MB

// ===========================================================================
// PTX helpers
// ===========================================================================
__device__ __forceinline__ uint32_t smem_u32(const void* p) {
    uint32_t a;
    asm("{ .reg .u64 t; cvta.to.shared.u64 t, %1; cvt.u32.u64 %0, t; }"
        : "=r"(a) : "l"(p));
    return a;
}
__device__ __forceinline__ void mma_tf32(float* d, const uint32_t* a,
                                         const uint32_t* b) {
    asm volatile(
        "mma.sync.aligned.m16n8k8.row.col.f32.tf32.tf32.f32 "
        "{%0,%1,%2,%3}, {%4,%5,%6,%7}, {%8,%9}, {%0,%1,%2,%3};"
        : "+f"(d[0]), "+f"(d[1]), "+f"(d[2]), "+f"(d[3])
        : "r"(a[0]), "r"(a[1]), "r"(a[2]), "r"(a[3]), "r"(b[0]), "r"(b[1]));
}
__device__ __forceinline__ void cp16(uint32_t smem, const void* g) {
    asm volatile("cp.async.cg.shared.global [%0], [%1], 16;"
                 :: "r"(smem), "l"(g) : "memory");
}
#define CP_COMMIT() asm volatile("cp.async.commit_group;" ::: "memory")
#define CP_WAIT1()  asm volatile("cp.async.wait_group 1;" ::: "memory")
#define CP_WAIT0()  asm volatile("cp.async.wait_group 0;" ::: "memory")
__device__ __forceinline__ uint32_t lds32(uint32_t addr) {
    uint32_t v;
    asm volatile("ld.shared.b32 %0, [%1];" : "=r"(v) : "r"(addr));
    return v;
}
__device__ __forceinline__ uint32_t f2tf32(float f) {
    uint32_t u;
    asm("cvt.rna.tf32.f32 %0, %1;" : "=r"(u) : "f"(f));
    return u;
}

// ===========================================================================
// Kernel 1: two-channel real-packed FFT, single inverse chain.
// z = x1 + i*x2 -> Z (13 fwd stages). U = N*ifft(M*Z), M keeps k<N/2
// (bit-rev position even). Then unmix using known x1, x2 and bins
// Z[0], Z[N/2] (bit-rev positions 0, 1):
//   R1' = N*x1 + Re(Z0) - Re(Z1)*(-1)^n   (prop. to Re(xa1))
//   R2' = N*x2 + Im(Z0) - Im(Z1)*(-1)^n   (prop. to Re(xa2))
//   ch1 = (R1', 2*Im(U) - R2') ; ch2 = (R2', R1' - 2*Re(U))
// then unit-normalize (scale cancels). 26 stages per 2 channels.
// ===========================================================================
__device__ __forceinline__ int swz(int i) { return i ^ ((i >> 5) & 31); }

template<int P, int LB, int FWD>
__device__ __forceinline__ void stage_one(float2 v[16], int base,
                                          const float2* __restrict__ tw) {
    const int s  = P + LB;
    const int bm = base & ((1 << s) - 1);
    float2 wc[(LB < 3) ? (1 << LB) : 1];
    if (LB < 3) {
#pragma unroll
        for (int q = 0; q < (1 << LB); q++)
            wc[q] = tw[(bm + (q << P)) << (12 - s)];
    }
#pragma unroll
    for (int rr = 0; rr < 16; rr++) {
        if ((rr >> LB) & 1) continue;
        const int r1 = rr | (1 << LB);
        float2 w;
        if (LB < 3) w = wc[rr & ((1 << LB) - 1)];
        else        w = tw[(bm + ((rr & 7) << P)) << (12 - s)];
        float2 a = v[rr], b = v[r1];
        if (FWD) {
            v[rr] = make_float2(a.x + b.x, a.y + b.y);
            float2 d = make_float2(a.x - b.x, a.y - b.y);
            v[r1] = make_float2(d.x * w.x - d.y * w.y, d.x * w.y + d.y * w.x);
        } else {
            float2 tt = make_float2(b.x * w.x + b.y * w.y, b.y * w.x - b.x * w.y);
            v[rr] = make_float2(a.x + tt.x, a.y + tt.y);
            v[r1] = make_float2(a.x - tt.x, a.y - tt.y);
        }
    }
}

template<int P, int FWD, int LBLO, int LBHI>
__device__ __forceinline__ void stages(float2 v[16], int base,
                                       const float2* __restrict__ tw) {
    if (FWD) {
        if (LBHI >= 3 && 3 >= LBLO) stage_one<P, 3, 1>(v, base, tw);
        if (LBHI >= 2 && 2 >= LBLO) stage_one<P, 2, 1>(v, base, tw);
        if (LBHI >= 1 && 1 >= LBLO) stage_one<P, 1, 1>(v, base, tw);
        if (LBHI >= 0 && 0 >= LBLO) stage_one<P, 0, 1>(v, base, tw);
    } else {
        if (LBLO <= 0 && 0 <= LBHI) stage_one<P, 0, 0>(v, base, tw);
        if (LBLO <= 1 && 1 <= LBHI) stage_one<P, 1, 0>(v, base, tw);
        if (LBLO <= 2 && 2 <= LBHI) stage_one<P, 2, 0>(v, base, tw);
        if (LBLO <= 3 && 3 <= LBHI) stage_one<P, 3, 0>(v, base, tw);
    }
}

extern __shared__ float2 smm[];
// layout (float2 units): [0..8191] exchange, [8192..12287] twiddles,
// [12288..20479] Xsave (input stash), [20480..20481] bin broadcast
// total = 20482 * 8 = 163856 bytes

__global__ void __launch_bounds__(512) fft_kernel(const float* __restrict__ x) {
    float2* sm  = smm;
    float2* tw  = smm + T_LEN;
    float2* Xsv = smm + T_LEN + HALF;
    float2* bc  = Xsv + T_LEN;
    const int tid = threadIdx.x;

    for (int t = tid; t < HALF; t += 512) {
        float s, c;
        sincosf(-6.283185307179586e0f * (float)t / (float)T_LEN, &s, &c);
        tw[t] = make_float2(c, s);
    }

    const int baseA = tid;                                  // P=9
    const int baseB = ((tid >> 5) << 9) + (tid & 31);       // P=5
    const int baseC = ((tid >> 1) << 5) + (tid & 1);        // P=1
    const int baseD = tid << 4;                             // P=0
    const int baseE = ((tid >> 4) << 8) + (tid & 15);       // P=4
    const int baseF = ((tid >> 8) << 12) + (tid & 255);     // P=8

    // Load z = x1 + i*x2 and stash input (thread-private; read back by
    // the same thread in the epilogue, so no extra syncs needed).
    const float* __restrict__ xr = x + (size_t)blockIdx.x * 2 * T_LEN;
    float2 v[16];
#pragma unroll
    for (int r = 0; r < 16; r++) {
        const int t = tid + (r << 9);
        v[r] = make_float2(xr[t], xr[T_LEN + t]);
        Xsv[t] = v[r];
    }
    __syncthreads();   // tw ready

    // ---- forward DIF: s = 12..0 (13 stages) ----
    stages<9, 1, 0, 3>(v, baseA, tw);
#pragma unroll
    for (int r = 0; r < 16; r++) sm[swz(baseA + (r << 9))] = v[r];
    __syncthreads();
#pragma unroll
    for (int r = 0; r < 16; r++) v[r] = sm[swz(baseB + (r << 5))];
    __syncthreads();
    stages<5, 1, 0, 3>(v, baseB, tw);
#pragma unroll
    for (int r = 0; r < 16; r++) sm[swz(baseB + (r << 5))] = v[r];
    __syncthreads();
#pragma unroll
    for (int r = 0; r < 16; r++) v[r] = sm[swz(baseC + (r << 1))];
    __syncthreads();
    stages<1, 1, 0, 3>(v, baseC, tw);
#pragma unroll
    for (int r = 0; r < 16; r++) sm[swz(baseC + (r << 1))] = v[r];
    __syncthreads();
#pragma unroll
    for (int r = 0; r < 16; r++) v[r] = sm[swz(baseD + r)];
    __syncthreads();
    stages<0, 1, 0, 0>(v, baseD, tw);       // fwd s=0 -> Z bit-reversed

    // Broadcast Z[0] (pos 0) and Z[N/2] (pos 1); synced by exchanges below.
    if (tid == 0) { bc[0] = v[0]; bc[1] = v[1]; }

    // ---- U = unnormalized ifft(M * Z): keep even bit-rev positions ----
#pragma unroll
    for (int r = 1; r < 16; r += 2) v[r] = make_float2(0.0f, 0.0f);

    stages<0, 0, 0, 3>(v, baseD, tw);       // s = 0..3
#pragma unroll
    for (int r = 0; r < 16; r++) sm[swz(baseD + r)] = v[r];
    __syncthreads();
#pragma unroll
    for (int r = 0; r < 16; r++) v[r] = sm[swz(baseE + (r << 4))];
    __syncthreads();
    stages<4, 0, 0, 3>(v, baseE, tw);       // s = 4..7
#pragma unroll
    for (int r = 0; r < 16; r++) sm[swz(baseE + (r << 4))] = v[r];
    __syncthreads();
#pragma unroll
    for (int r = 0; r < 16; r++) v[r] = sm[swz(baseF + (r << 8))];
    __syncthreads();
    stages<8, 0, 0, 3>(v, baseF, tw);       // s = 8..11
#pragma unroll
    for (int r = 0; r < 16; r++) sm[swz(baseF + (r << 8))] = v[r];
    __syncthreads();
#pragma unroll
    for (int r = 0; r < 16; r++) v[r] = sm[swz(baseA + (r << 9))];
    __syncthreads();
    stages<9, 0, 3, 3>(v, baseA, tw);       // s = 12 -> natural order

    // ---- unmix, normalize, store both channels (tf32) ----
    const float2 Z0 = bc[0];
    const float2 Z1 = bc[1];
    const float par = (tid & 1) ? -1.0f : 1.0f;   // (-1)^n, n = tid + 512r
    const float Nf = (float)T_LEN;
    const float b1 = Z0.x - Z1.x * par;           // Re(Z0) - Re(Z1)*(-1)^n
    const float b2 = Z0.y - Z1.y * par;
    const size_t row0 = (size_t)blockIdx.x * 2 * T_LEN;
#pragma unroll
    for (int r = 0; r < 16; r++) {
        const int t = tid + (r << 9);
        float2 U  = v[r];
        float2 xi = Xsv[t];
        float R1 = fmaf(Nf, xi.x, b1);            // 2N*Re(xa1)
        float R2 = fmaf(Nf, xi.y, b2);            // 2N*Re(xa2)
        float I1 = 2.0f * U.y - R2;               // 2N*Im(xa1)
        float I2 = R1 - 2.0f * U.x;               // 2N*Im(xa2)

        float m1 = R1 * R1 + I1 * I1;
        float c1, s1;
        if (m1 > 0.0f) { float iv = rsqrtf(m1); c1 = R1 * iv; s1 = I1 * iv; }
        else           { c1 = 1.0f; s1 = 0.0f; }
        float m2 = R2 * R2 + I2 * I2;
        float c2, s2;
        if (m2 > 0.0f) { float iv = rsqrtf(m2); c2 = R2 * iv; s2 = I2 * iv; }
        else           { c2 = 1.0f; s2 = 0.0f; }

        g_c[row0 + t]         = __uint_as_float(f2tf32(c1));
        g_s[row0 + t]         = __uint_as_float(f2tf32(s1));
        g_c[row0 + T_LEN + t] = __uint_as_float(f2tf32(c2));
        g_s[row0 + T_LEN + t] = __uint_as_float(f2tf32(s2));
    }
}

// ===========================================================================
// Kernel 2: tf32 single-chain Gram via mma.sync.m16n8k8 (unchanged from R11).
// CTA = (ks, q, b). q: 0=CC (A=B=cos), 1=SS (A=B=sin), 2=SC (A=sin, B=cos).
// ===========================================================================
extern __shared__ __align__(128) char gsm[];   // 2 * BUFB = 73728 B

__global__ void __launch_bounds__(256, 2) gram_tf32() {
    const int tid  = threadIdx.x;
    const int wid  = tid >> 5;
    const int lane = tid & 31;
    const int ks   = blockIdx.x;
    const int q    = blockIdx.y;
    const int b    = blockIdx.z;
    const bool diag = (q < 2);

    const float* __restrict__ srcA = (q == 0) ? g_c : g_s;
    const float* __restrict__ srcB = (q == 1) ? g_s : g_c;

    const uint32_t sb = smem_u32(gsm);
    const size_t k0 = (size_t)ks * (T_LEN / KSPLIT);

    const int qi  = tid & 7;
    const int r32 = tid >> 3;
    const int npass = diag ? 4 : 8;

    const float* psrc[8]; uint32_t pdst[8];
#pragma unroll
    for (int p = 0; p < 8; p++) {
        const int row = r32 + (p & 3) * 32;
        const float* srcm = (p < 4) ? srcA : srcB;
        psrc[p] = srcm + (size_t)(b * CH + row) * T_LEN + k0 + qi * 4;
        pdst[p] = (uint32_t)((p < 4 ? 0 : BOFF) + row * ROWB + qi * 16);
    }

    auto load_chunk = [&](int c) {
        const uint32_t bufb = sb + (uint32_t)((c & 1) * BUFB);
        const int kofs = c * KC;
#pragma unroll
        for (int p = 0; p < 8; p++) {
            if (p >= npass) break;
            cp16(bufb + pdst[p], psrc[p] + kofs);
        }
        CP_COMMIT();
    };

    const int mrow0 = (wid >> 2) * 64;
    const int ncol0 = (wid & 3) * 32;
    const uint32_t bOfs = diag ? 0u : (uint32_t)BOFF;

    float acc[4][4][4];
#pragma unroll
    for (int mt = 0; mt < 4; mt++)
#pragma unroll
        for (int nt = 0; nt < 4; nt++)
#pragma unroll
            for (int e = 0; e < 4; e++) acc[mt][nt][e] = 0.0f;

    const int lg = lane >> 2;
    const int lk = lane & 3;

    load_chunk(0);
    for (int c = 0; c < NCHUNK; c++) {
        if (c + 1 < NCHUNK) { load_chunk(c + 1); CP_WAIT1(); }
        else                { CP_WAIT0(); }
        __syncthreads();

        const uint32_t bufb = sb + (uint32_t)((c & 1) * BUFB);
#pragma unroll
        for (int kstep = 0; kstep < KC / 8; kstep++) {
            const uint32_t kb = (uint32_t)(kstep * 32 + lk * 4);
            uint32_t bfr[4][2];
#pragma unroll
            for (int nt = 0; nt < 4; nt++) {
                const uint32_t ba =
                    bufb + bOfs + (uint32_t)((ncol0 + nt * 8 + lg) * ROWB) + kb;
                bfr[nt][0] = lds32(ba);
                bfr[nt][1] = lds32(ba + 16);
            }
#pragma unroll
            for (int mt = 0; mt < 4; mt++) {
                const uint32_t aa =
                    bufb + (uint32_t)((mrow0 + mt * 16 + lg) * ROWB) + kb;
                uint32_t af[4];
                af[0] = lds32(aa);
                af[1] = lds32(aa + 8 * ROWB);
                af[2] = lds32(aa + 16);
                af[3] = lds32(aa + 8 * ROWB + 16);
#pragma unroll
                for (int nt = 0; nt < 4; nt++)
                    mma_tf32(acc[mt][nt], af, bfr[nt]);
            }
        }
        __syncthreads();
    }

    float* __restrict__ G =
        g_gram + ((size_t)((ks * BATCH + b) * 3 + q)) * (CH * CH);
    const int r0 = lane >> 2;
    const int c0 = (lane & 3) * 2;
#pragma unroll
    for (int mt = 0; mt < 4; mt++) {
        const int row = mrow0 + mt * 16 + r0;
#pragma unroll
        for (int nt = 0; nt < 4; nt++) {
            const int col = ncol0 + nt * 8 + c0;
            *(float2*)(G + row * CH + col) =
                make_float2(acc[mt][nt][0], acc[mt][nt][1]);
            *(float2*)(G + (row + 8) * CH + col) =
                make_float2(acc[mt][nt][2], acc[mt][nt][3]);
        }
    }
}

// ===========================================================================
// Kernel 3: combine K-splits; Re = CC+SS, Im = SC_ij - SC_ji; PLV = |.|/T.
// ===========================================================================
__global__ void finalize_kernel(float* __restrict__ out) {
    const int idx = blockIdx.x * blockDim.x + threadIdx.x;
    if (idx >= BATCH * CH * CH) return;
    const int b  = idx >> 14;
    const int ij = idx & 16383;
    const int i  = ij >> 7;
    const int j  = ij & 127;
    float re = 0.0f, im = 0.0f;
#pragma unroll
    for (int ks = 0; ks < KSPLIT; ks++) {
        const float* __restrict__ base =
            g_gram + ((size_t)((ks * BATCH + b) * 3)) * (CH * CH);
        re += base[ij] + base[CH * CH + ij];                       // CC + SS
        im += base[2 * CH * CH + i * CH + j]
            - base[2 * CH * CH + j * CH + i];                      // SC - SC^T
    }
    out[idx] = sqrtf(re * re + im * im) * (1.0f / (float)T_LEN);
}

// ===========================================================================
extern "C" void kernel_launch(void* const* d_in, const int* in_sizes, int n_in,
                              void* d_out, int out_size) {
    const float* x = (const float*)d_in[0];
    float* out = (float*)d_out;

    const int fft_smem = (2 * T_LEN + HALF + 2) * (int)sizeof(float2); // 163856
    cudaFuncSetAttribute(fft_kernel, cudaFuncAttributeMaxDynamicSharedMemorySize,
                         fft_smem);
    cudaFuncSetAttribute(gram_tf32, cudaFuncAttributeMaxDynamicSharedMemorySize,
                         2 * BUFB);

    fft_kernel<<<NSIG / 2, 512, fft_smem>>>(x);
    gram_tf32<<<dim3(KSPLIT, 3, BATCH), 256, 2 * BUFB>>>();
    finalize_kernel<<<(BATCH * CH * CH + 255) / 256, 256>>>(out);
}

// round 15
// speedup vs baseline: 1.4650x; 1.0186x over previous
#include <cuda_runtime.h>
#include <math.h>
#include <stdint.h>

#define T_LEN 8192
#define HALF  4096
#define CH    128
#define BATCH 16
#define NSIG  (BATCH * CH)

#define KSPLIT 16
#define KC     32                          // fp32 per chunk = 128 B rows
#define NCHUNK ((T_LEN / KSPLIT) / KC)     // 16
#define ROWB   144                         // 128B data + 16B pad (conflict-free)
#define BOFF   (128 * ROWB)                // 18432
#define BUFB   (2 * 128 * ROWB)            // 36864 per buffer

// Scratch (alloc-free rule: __device__ globals)
__device__ float g_c[(size_t)BATCH * CH * T_LEN];             // cos(phase): 64 MB
__device__ float g_s[(size_t)BATCH * CH * T_LEN];             // sin(phase): 64 MB
__device__ float g_gram[(size_t)KSPLIT * BATCH * 3 * CH * CH];// tiles: 50 MB

// ===========================================================================
// PTX helpers
// ===========================================================================
__device__ __forceinline__ uint32_t smem_u32(const void* p) {
    uint32_t a;
    asm("{ .reg .u64 t; cvta.to.shared.u64 t, %1; cvt.u32.u64 %0, t; }"
        : "=r"(a) : "l"(p));
    return a;
}
__device__ __forceinline__ void mma_tf32(float* d, const uint32_t* a,
                                         const uint32_t* b) {
    asm volatile(
        "mma.sync.aligned.m16n8k8.row.col.f32.tf32.tf32.f32 "
        "{%0,%1,%2,%3}, {%4,%5,%6,%7}, {%8,%9}, {%0,%1,%2,%3};"
        : "+f"(d[0]), "+f"(d[1]), "+f"(d[2]), "+f"(d[3])
        : "r"(a[0]), "r"(a[1]), "r"(a[2]), "r"(a[3]), "r"(b[0]), "r"(b[1]));
}
__device__ __forceinline__ void cp16(uint32_t smem, const void* g) {
    asm volatile("cp.async.cg.shared.global [%0], [%1], 16;"
                 :: "r"(smem), "l"(g) : "memory");
}
#define CP_COMMIT() asm volatile("cp.async.commit_group;" ::: "memory")
#define CP_WAIT1()  asm volatile("cp.async.wait_group 1;" ::: "memory")
#define CP_WAIT0()  asm volatile("cp.async.wait_group 0;" ::: "memory")
__device__ __forceinline__ uint32_t lds32(uint32_t addr) {
    uint32_t v;
    asm volatile("ld.shared.b32 %0, [%1];" : "=r"(v) : "r"(addr));
    return v;
}
__device__ __forceinline__ uint32_t f2tf32(float f) {
    uint32_t u;
    asm("cvt.rna.tf32.f32 %0, %1;" : "=r"(u) : "f"(f));
    return u;
}

// ===========================================================================
// Kernel 1: two-channel real-packed FFT, single inverse chain.
// z = x1 + i*x2 -> Z (13 fwd stages). U = N*ifft(M*Z), M keeps k<N/2
// (bit-rev position even). Unmix with stashed x1,x2 and bins Z[0],Z[N/2].
// Input stashed in REGISTERS (same-thread, same-index round trip).
// Inverse stage 0 is a copy (masked odd positions are zero) - skipped.
// ===========================================================================
__device__ __forceinline__ int swz(int i) { return i ^ ((i >> 5) & 31); }

template<int P, int LB, int FWD>
__device__ __forceinline__ void stage_one(float2 v[16], int base,
                                          const float2* __restrict__ tw) {
    const int s  = P + LB;
    const int bm = base & ((1 << s) - 1);
    float2 wc[(LB < 3) ? (1 << LB) : 1];
    if (LB < 3) {
#pragma unroll
        for (int q = 0; q < (1 << LB); q++)
            wc[q] = tw[(bm + (q << P)) << (12 - s)];
    }
#pragma unroll
    for (int rr = 0; rr < 16; rr++) {
        if ((rr >> LB) & 1) continue;
        const int r1 = rr | (1 << LB);
        float2 w;
        if (LB < 3) w = wc[rr & ((1 << LB) - 1)];
        else        w = tw[(bm + ((rr & 7) << P)) << (12 - s)];
        float2 a = v[rr], b = v[r1];
        if (FWD) {
            v[rr] = make_float2(a.x + b.x, a.y + b.y);
            float2 d = make_float2(a.x - b.x, a.y - b.y);
            v[r1] = make_float2(d.x * w.x - d.y * w.y, d.x * w.y + d.y * w.x);
        } else {
            float2 tt = make_float2(b.x * w.x + b.y * w.y, b.y * w.x - b.x * w.y);
            v[rr] = make_float2(a.x + tt.x, a.y + tt.y);
            v[r1] = make_float2(a.x - tt.x, a.y - tt.y);
        }
    }
}

template<int P, int FWD, int LBLO, int LBHI>
__device__ __forceinline__ void stages(float2 v[16], int base,
                                       const float2* __restrict__ tw) {
    if (FWD) {
        if (LBHI >= 3 && 3 >= LBLO) stage_one<P, 3, 1>(v, base, tw);
        if (LBHI >= 2 && 2 >= LBLO) stage_one<P, 2, 1>(v, base, tw);
        if (LBHI >= 1 && 1 >= LBLO) stage_one<P, 1, 1>(v, base, tw);
        if (LBHI >= 0 && 0 >= LBLO) stage_one<P, 0, 1>(v, base, tw);
    } else {
        if (LBLO <= 0 && 0 <= LBHI) stage_one<P, 0, 0>(v, base, tw);
        if (LBLO <= 1 && 1 <= LBHI) stage_one<P, 1, 0>(v, base, tw);
        if (LBLO <= 2 && 2 <= LBHI) stage_one<P, 2, 0>(v, base, tw);
        if (LBLO <= 3 && 3 <= LBHI) stage_one<P, 3, 0>(v, base, tw);
    }
}

extern __shared__ float2 smm[];
// layout (float2 units): [0..8191] exchange, [8192..12287] twiddles,
// [12288..12289] bin broadcast -> 98320 bytes total

__global__ void __launch_bounds__(512) fft_kernel(const float* __restrict__ x) {
    float2* sm = smm;
    float2* tw = smm + T_LEN;
    float2* bc = smm + T_LEN + HALF;
    const int tid = threadIdx.x;

    for (int t = tid; t < HALF; t += 512) {
        float s, c;
        sincosf(-6.283185307179586e0f * (float)t / (float)T_LEN, &s, &c);
        tw[t] = make_float2(c, s);
    }

    const int baseA = tid;                                  // P=9
    const int baseB = ((tid >> 5) << 9) + (tid & 31);       // P=5
    const int baseC = ((tid >> 1) << 5) + (tid & 1);        // P=1
    const int baseD = tid << 4;                             // P=0
    const int baseE = ((tid >> 4) << 8) + (tid & 15);       // P=4
    const int baseF = ((tid >> 8) << 12) + (tid & 255);     // P=8

    // Load z = x1 + i*x2; stash input in registers (same thread reads the
    // same indices t = tid + (r<<9) in the epilogue).
    const float* __restrict__ xr = x + (size_t)blockIdx.x * 2 * T_LEN;
    float2 v[16];
    float x1s[16], x2s[16];
#pragma unroll
    for (int r = 0; r < 16; r++) {
        const int t = tid + (r << 9);
        float a = xr[t], b = xr[T_LEN + t];
        v[r] = make_float2(a, b);
        x1s[r] = a; x2s[r] = b;
    }
    __syncthreads();   // tw ready

    // ---- forward DIF: s = 12..0 (13 stages) ----
    stages<9, 1, 0, 3>(v, baseA, tw);
#pragma unroll
    for (int r = 0; r < 16; r++) sm[swz(baseA + (r << 9))] = v[r];
    __syncthreads();
#pragma unroll
    for (int r = 0; r < 16; r++) v[r] = sm[swz(baseB + (r << 5))];
    __syncthreads();
    stages<5, 1, 0, 3>(v, baseB, tw);
#pragma unroll
    for (int r = 0; r < 16; r++) sm[swz(baseB + (r << 5))] = v[r];
    __syncthreads();
#pragma unroll
    for (int r = 0; r < 16; r++) v[r] = sm[swz(baseC + (r << 1))];
    __syncthreads();
    stages<1, 1, 0, 3>(v, baseC, tw);
#pragma unroll
    for (int r = 0; r < 16; r++) sm[swz(baseC + (r << 1))] = v[r];
    __syncthreads();
#pragma unroll
    for (int r = 0; r < 16; r++) v[r] = sm[swz(baseD + r)];
    __syncthreads();
    stages<0, 1, 0, 0>(v, baseD, tw);       // fwd s=0 -> Z bit-reversed

    // Broadcast Z[0] (pos 0) and Z[N/2] (pos 1); synced by exchanges below.
    if (tid == 0) { bc[0] = v[0]; bc[1] = v[1]; }

    // ---- U = unnormalized ifft(M * Z): keep even bit-rev positions.
    // Mask odd + inverse stage 0 fuse to a copy: v[r+1] = v[r].
#pragma unroll
    for (int r = 0; r < 16; r += 2) v[r + 1] = v[r];

    stages<0, 0, 1, 3>(v, baseD, tw);       // s = 1..3
#pragma unroll
    for (int r = 0; r < 16; r++) sm[swz(baseD + r)] = v[r];
    __syncthreads();
#pragma unroll
    for (int r = 0; r < 16; r++) v[r] = sm[swz(baseE + (r << 4))];
    __syncthreads();
    stages<4, 0, 0, 3>(v, baseE, tw);       // s = 4..7
#pragma unroll
    for (int r = 0; r < 16; r++) sm[swz(baseE + (r << 4))] = v[r];
    __syncthreads();
#pragma unroll
    for (int r = 0; r < 16; r++) v[r] = sm[swz(baseF + (r << 8))];
    __syncthreads();
    stages<8, 0, 0, 3>(v, baseF, tw);       // s = 8..11
#pragma unroll
    for (int r = 0; r < 16; r++) sm[swz(baseF + (r << 8))] = v[r];
    __syncthreads();
#pragma unroll
    for (int r = 0; r < 16; r++) v[r] = sm[swz(baseA + (r << 9))];
    __syncthreads();
    stages<9, 0, 3, 3>(v, baseA, tw);       // s = 12 -> natural order

    // ---- unmix, normalize, store both channels (tf32) ----
    const float2 Z0 = bc[0];
    const float2 Z1 = bc[1];
    const float par = (tid & 1) ? -1.0f : 1.0f;   // (-1)^n, n = tid + 512r
    const float Nf = (float)T_LEN;
    const float b1 = Z0.x - Z1.x * par;           // Re(Z0) - Re(Z1)*(-1)^n
    const float b2 = Z0.y - Z1.y * par;
    const size_t row0 = (size_t)blockIdx.x * 2 * T_LEN;
#pragma unroll
    for (int r = 0; r < 16; r++) {
        const int t = tid + (r << 9);
        float2 U = v[r];
        float R1 = fmaf(Nf, x1s[r], b1);          // 2N*Re(xa1)
        float R2 = fmaf(Nf, x2s[r], b2);          // 2N*Re(xa2)
        float I1 = 2.0f * U.y - R2;               // 2N*Im(xa1)
        float I2 = R1 - 2.0f * U.x;               // 2N*Im(xa2)

        float m1 = R1 * R1 + I1 * I1;
        float c1, s1;
        if (m1 > 0.0f) { float iv = rsqrtf(m1); c1 = R1 * iv; s1 = I1 * iv; }
        else           { c1 = 1.0f; s1 = 0.0f; }
        float m2 = R2 * R2 + I2 * I2;
        float c2, s2;
        if (m2 > 0.0f) { float iv = rsqrtf(m2); c2 = R2 * iv; s2 = I2 * iv; }
        else           { c2 = 1.0f; s2 = 0.0f; }

        g_c[row0 + t]         = __uint_as_float(f2tf32(c1));
        g_s[row0 + t]         = __uint_as_float(f2tf32(s1));
        g_c[row0 + T_LEN + t] = __uint_as_float(f2tf32(c2));
        g_s[row0 + T_LEN + t] = __uint_as_float(f2tf32(s2));
    }
}

// ===========================================================================
// Kernel 2: tf32 single-chain Gram via mma.sync.m16n8k8 (unchanged from R11).
// CTA = (ks, q, b). q: 0=CC (A=B=cos), 1=SS (A=B=sin), 2=SC (A=sin, B=cos).
// ===========================================================================
extern __shared__ __align__(128) char gsm[];   // 2 * BUFB = 73728 B

__global__ void __launch_bounds__(256, 2) gram_tf32() {
    const int tid  = threadIdx.x;
    const int wid  = tid >> 5;
    const int lane = tid & 31;
    const int ks   = blockIdx.x;
    const int q    = blockIdx.y;
    const int b    = blockIdx.z;
    const bool diag = (q < 2);

    const float* __restrict__ srcA = (q == 0) ? g_c : g_s;
    const float* __restrict__ srcB = (q == 1) ? g_s : g_c;

    const uint32_t sb = smem_u32(gsm);
    const size_t k0 = (size_t)ks * (T_LEN / KSPLIT);

    const int qi  = tid & 7;
    const int r32 = tid >> 3;
    const int npass = diag ? 4 : 8;

    const float* psrc[8]; uint32_t pdst[8];
#pragma unroll
    for (int p = 0; p < 8; p++) {
        const int row = r32 + (p & 3) * 32;
        const float* srcm = (p < 4) ? srcA : srcB;
        psrc[p] = srcm + (size_t)(b * CH + row) * T_LEN + k0 + qi * 4;
        pdst[p] = (uint32_t)((p < 4 ? 0 : BOFF) + row * ROWB + qi * 16);
    }

    auto load_chunk = [&](int c) {
        const uint32_t bufb = sb + (uint32_t)((c & 1) * BUFB);
        const int kofs = c * KC;
#pragma unroll
        for (int p = 0; p < 8; p++) {
            if (p >= npass) break;
            cp16(bufb + pdst[p], psrc[p] + kofs);
        }
        CP_COMMIT();
    };

    const int mrow0 = (wid >> 2) * 64;
    const int ncol0 = (wid & 3) * 32;
    const uint32_t bOfs = diag ? 0u : (uint32_t)BOFF;

    float acc[4][4][4];
#pragma unroll
    for (int mt = 0; mt < 4; mt++)
#pragma unroll
        for (int nt = 0; nt < 4; nt++)
#pragma unroll
            for (int e = 0; e < 4; e++) acc[mt][nt][e] = 0.0f;

    const int lg = lane >> 2;
    const int lk = lane & 3;

    load_chunk(0);
    for (int c = 0; c < NCHUNK; c++) {
        if (c + 1 < NCHUNK) { load_chunk(c + 1); CP_WAIT1(); }
        else                { CP_WAIT0(); }
        __syncthreads();

        const uint32_t bufb = sb + (uint32_t)((c & 1) * BUFB);
#pragma unroll
        for (int kstep = 0; kstep < KC / 8; kstep++) {
            const uint32_t kb = (uint32_t)(kstep * 32 + lk * 4);
            uint32_t bfr[4][2];
#pragma unroll
            for (int nt = 0; nt < 4; nt++) {
                const uint32_t ba =
                    bufb + bOfs + (uint32_t)((ncol0 + nt * 8 + lg) * ROWB) + kb;
                bfr[nt][0] = lds32(ba);
                bfr[nt][1] = lds32(ba + 16);
            }
#pragma unroll
            for (int mt = 0; mt < 4; mt++) {
                const uint32_t aa =
                    bufb + (uint32_t)((mrow0 + mt * 16 + lg) * ROWB) + kb;
                uint32_t af[4];
                af[0] = lds32(aa);
                af[1] = lds32(aa + 8 * ROWB);
                af[2] = lds32(aa + 16);
                af[3] = lds32(aa + 8 * ROWB + 16);
#pragma unroll
                for (int nt = 0; nt < 4; nt++)
                    mma_tf32(acc[mt][nt], af, bfr[nt]);
            }
        }
        __syncthreads();
    }

    float* __restrict__ G =
        g_gram + ((size_t)((ks * BATCH + b) * 3 + q)) * (CH * CH);
    const int r0 = lane >> 2;
    const int c0 = (lane & 3) * 2;
#pragma unroll
    for (int mt = 0; mt < 4; mt++) {
        const int row = mrow0 + mt * 16 + r0;
#pragma unroll
        for (int nt = 0; nt < 4; nt++) {
            const int col = ncol0 + nt * 8 + c0;
            *(float2*)(G + row * CH + col) =
                make_float2(acc[mt][nt][0], acc[mt][nt][1]);
            *(float2*)(G + (row + 8) * CH + col) =
                make_float2(acc[mt][nt][2], acc[mt][nt][3]);
        }
    }
}

// ===========================================================================
// Kernel 3: combine K-splits; Re = CC+SS, Im = SC_ij - SC_ji; PLV = |.|/T.
// ===========================================================================
__global__ void finalize_kernel(float* __restrict__ out) {
    const int idx = blockIdx.x * blockDim.x + threadIdx.x;
    if (idx >= BATCH * CH * CH) return;
    const int b  = idx >> 14;
    const int ij = idx & 16383;
    const int i  = ij >> 7;
    const int j  = ij & 127;
    float re = 0.0f, im = 0.0f;
#pragma unroll
    for (int ks = 0; ks < KSPLIT; ks++) {
        const float* __restrict__ base =
            g_gram + ((size_t)((ks * BATCH + b) * 3)) * (CH * CH);
        re += base[ij] + base[CH * CH + ij];                       // CC + SS
        im += base[2 * CH * CH + i * CH + j]
            - base[2 * CH * CH + j * CH + i];                      // SC - SC^T
    }
    out[idx] = sqrtf(re * re + im * im) * (1.0f / (float)T_LEN);
}

// ===========================================================================
extern "C" void kernel_launch(void* const* d_in, const int* in_sizes, int n_in,
                              void* d_out, int out_size) {
    const float* x = (const float*)d_in[0];
    float* out = (float*)d_out;

    const int fft_smem = (T_LEN + HALF + 2) * (int)sizeof(float2); // 98320
    cudaFuncSetAttribute(fft_kernel, cudaFuncAttributeMaxDynamicSharedMemorySize,
                         fft_smem);
    cudaFuncSetAttribute(gram_tf32, cudaFuncAttributeMaxDynamicSharedMemorySize,
                         2 * BUFB);

    fft_kernel<<<NSIG / 2, 512, fft_smem>>>(x);
    gram_tf32<<<dim3(KSPLIT, 3, BATCH), 256, 2 * BUFB>>>();
    finalize_kernel<<<(BATCH * CH * CH + 255) / 256, 256>>>(out);
}